// round 4
// baseline (speedup 1.0000x reference)
#include <cuda_runtime.h>
#include <cuda_bf16.h>
#include <cstdint>

// ---------------------------------------------------------------------------
// FeatherNet via mma.sync bf16 HMMA. Split-bf16 3-pass (hi*hi + hi*lo + lo*hi)
// fp32 accumulate. K-chunk 32, 2-stage cp.async ring, 2 CTAs/SM.
// Biases computed by a separate fp32 dot-product kernel (no fp32 V plane).
// ---------------------------------------------------------------------------

using bf16 = __nv_bfloat16;

#define D_IN   2048
#define D_FF   8192
#define D_OUT  2048
#define BATCH  4096
#define SZN    5794
#define SZM    2897
#define SZN_PAD 5888            // 46*128
#define SZK_PAD 2944            // 92*32

#define OFF_B1 (D_FF * D_IN)                // 16777216
#define OFF_W2 (OFF_B1 + D_FF)              // 16785408
#define OFF_B2 (OFF_W2 + D_OUT * D_FF)      // 33562624

// ---------------- device scratch -------------------------------------------
__device__ bf16  g_V1hi[(size_t)SZN_PAD * SZK_PAD];
__device__ bf16  g_V1lo[(size_t)SZN_PAD * SZK_PAD];
__device__ bf16  g_V2hi[(size_t)SZN_PAD * SZK_PAD];
__device__ bf16  g_V2lo[(size_t)SZN_PAD * SZK_PAD];
__device__ bf16  g_Vhi[(size_t)SZN * SZN];
__device__ bf16  g_Vlo[(size_t)SZN * SZN];
__device__ bf16  g_xhi[(size_t)BATCH * D_IN];
__device__ bf16  g_xlo[(size_t)BATCH * D_IN];
__device__ bf16  g_hhi[(size_t)BATCH * D_FF];
__device__ bf16  g_hlo[(size_t)BATCH * D_FF];
__device__ float g_bias[D_FF + D_OUT];      // [b1 | b2]

// ---------------- PTX helpers ----------------------------------------------
__device__ __forceinline__ uint32_t smem_u32(const void* p) {
    uint32_t a;
    asm("{ .reg .u64 t; cvta.to.shared.u64 t, %1; cvt.u32.u64 %0, t; }"
        : "=r"(a) : "l"(p));
    return a;
}

#define CP16(sm, gp) \
    asm volatile("cp.async.cg.shared.global [%0], [%1], 16;" :: "r"(sm), "l"(gp))
#define CPCOMMIT() asm volatile("cp.async.commit_group;" ::: "memory")
#define CPWAIT0()  asm volatile("cp.async.wait_group 0;" ::: "memory")

#define LDSM4(r0, r1, r2, r3, addr) \
    asm volatile("ldmatrix.sync.aligned.m8n8.x4.shared.b16 {%0,%1,%2,%3}, [%4];" \
                 : "=r"(r0), "=r"(r1), "=r"(r2), "=r"(r3) : "r"(addr))

#define MMA(d, a, b0r, b1r) \
    asm volatile("mma.sync.aligned.m16n8k16.row.col.f32.bf16.bf16.f32 " \
                 "{%0,%1,%2,%3}, {%4,%5,%6,%7}, {%8,%9}, {%0,%1,%2,%3};" \
                 : "+f"((d)[0]), "+f"((d)[1]), "+f"((d)[2]), "+f"((d)[3]) \
                 : "r"((a)[0]), "r"((a)[1]), "r"((a)[2]), "r"((a)[3]), \
                   "r"(b0r), "r"(b1r))

// ---------------- tiling ---------------------------------------------------
// CTA tile 128x128, K-chunk 32. Plane: [128 rows][32 k elems], row stride 80B
// (64 data + 16 pad -> conflict-free LDSM: 5 coprime 8). 2-stage ring.
#define TK        32
#define ROWB      80
#define PLANE     (128 * ROWB)          // 10240 B
#define OFF_SA_HI 0
#define OFF_SA_LO PLANE
#define OFF_SB_HI (2 * PLANE)
#define OFF_SB_LO (3 * PLANE)
#define STAGE     (4 * PLANE)           // 40960 B
#define SMEM_TOTAL (2 * STAGE)          // 81920 B -> 2 CTAs/SM

// ---------------------------------------------------------------------------
__global__ void split_pad(const float* __restrict__ src,
                          bf16* __restrict__ hi, bf16* __restrict__ lo,
                          int rows, int cols, int prows, int pcols)
{
    int idx = blockIdx.x * blockDim.x + threadIdx.x;
    int total = prows * pcols;
    if (idx >= total) return;
    int r = idx / pcols;
    int c = idx - r * pcols;
    float v = (r < rows && c < cols) ? src[(size_t)r * cols + c] : 0.0f;
    bf16 h = __float2bfloat16(v);
    hi[idx] = h;
    lo[idx] = __float2bfloat16(v - __bfloat162float(h));
}

// ---------------------------------------------------------------------------
// bias: out[j] = dot(V1[r,:], V2[c,:]) fp32, warp per output.
// j < D_FF: flat = OFF_B1 + j; else flat = OFF_B2 + (j - D_FF).
// ---------------------------------------------------------------------------
__global__ void bias_kernel(const float* __restrict__ V1, const float* __restrict__ V2,
                            float* __restrict__ biases)
{
    int w = (blockIdx.x * blockDim.x + threadIdx.x) >> 5;
    int lane = threadIdx.x & 31;
    if (w >= D_FF + D_OUT) return;
    size_t flat = (w < D_FF) ? ((size_t)OFF_B1 + w) : ((size_t)OFF_B2 + (w - D_FF));
    int r = (int)(flat / SZN);
    int c = (int)(flat - (size_t)r * SZN);
    const float* a = V1 + (size_t)r * SZM;
    const float* b = V2 + (size_t)c * SZM;
    float s = 0.0f;
    for (int k = lane; k < SZM; k += 32)
        s = fmaf(__ldg(a + k), __ldg(b + k), s);
    #pragma unroll
    for (int o = 16; o > 0; o >>= 1)
        s += __shfl_xor_sync(0xFFFFFFFFu, s, o);
    if (lane == 0) biases[w] = s;
}

// ---------------------------------------------------------------------------
// split-bf16 HMMA GEMM: C[M,N] = A @ B^T (+bias) (relu)
// ---------------------------------------------------------------------------
template<bool BIAS, bool RELU, bool STF32, bool HILO, bool BOUND>
__global__ __launch_bounds__(256, 2)
void gemm_mma(const bf16* __restrict__ Ahi, const bf16* __restrict__ Alo,
              const bf16* __restrict__ Bhi, const bf16* __restrict__ Blo,
              const float* __restrict__ bias,
              float* __restrict__ C, bf16* __restrict__ Chi, bf16* __restrict__ Clo,
              int M, int N, int K, int lda, int ldb, int ldc)
{
    extern __shared__ char smem[];
    const uint32_t sb = smem_u32(smem);
    const int tid  = threadIdx.x;
    const int lane = tid & 31, wid = tid >> 5;
    const int wm = wid >> 2;        // 0..1 : 64 rows
    const int wn = wid & 3;         // 0..3 : 32 cols
    const int brow = blockIdx.y * 128;
    const int bcol = blockIdx.x * 128;

    // cp.async geometry: 1 thread per (row, 32B half-row)
    const int prow = tid & 127;
    const int pcB  = (tid >> 7) * 32;               // byte col in plane row
    const int pcE  = (tid >> 7) * 16;               // elem col in source row
    const bf16* gAh = Ahi + (size_t)(brow + prow) * lda + pcE;
    const bf16* gAl = Alo + (size_t)(brow + prow) * lda + pcE;
    const bf16* gBh = Bhi + (size_t)(bcol + prow) * ldb + pcE;
    const bf16* gBl = Blo + (size_t)(bcol + prow) * ldb + pcE;
    const uint32_t stByte = (uint32_t)(prow * ROWB + pcB);

    const uint32_t aByte = (uint32_t)((wm * 64 + (lane & 15)) * ROWB + (lane >> 4) * 16);
    const uint32_t bByte = (uint32_t)((wn * 32 + (lane & 15)) * ROWB + (lane >> 4) * 16);

    float acc[4][4][4];
    #pragma unroll
    for (int t = 0; t < 4; ++t)
        #pragma unroll
        for (int u = 0; u < 4; ++u)
            #pragma unroll
            for (int e = 0; e < 4; ++e) acc[t][u][e] = 0.0f;

    const int nk = K / TK;

    auto issue = [&](int kb) {
        const uint32_t st = sb + (uint32_t)(kb & 1) * STAGE + stByte;
        const size_t go = (size_t)kb * TK;
        CP16(st + OFF_SA_HI,      gAh + go);
        CP16(st + OFF_SA_HI + 16, gAh + go + 8);
        CP16(st + OFF_SA_LO,      gAl + go);
        CP16(st + OFF_SA_LO + 16, gAl + go + 8);
        CP16(st + OFF_SB_HI,      gBh + go);
        CP16(st + OFF_SB_HI + 16, gBh + go + 8);
        CP16(st + OFF_SB_LO,      gBl + go);
        CP16(st + OFF_SB_LO + 16, gBl + go + 8);
        CPCOMMIT();
    };

    issue(0);

    #pragma unroll 1
    for (int i = 0; i < nk; ++i) {
        CPWAIT0();
        __syncthreads();
        if (i + 1 < nk) issue(i + 1);
        const uint32_t st = sb + (uint32_t)(i & 1) * STAGE;

        #pragma unroll
        for (int ks = 0; ks < 2; ++ks) {
            const uint32_t ko = (uint32_t)ks * 32;
            uint32_t bh[8], bl[8], af[16];
            LDSM4(bh[0], bh[1], bh[2], bh[3], st + OFF_SB_HI + bByte + ko);
            LDSM4(bh[4], bh[5], bh[6], bh[7], st + OFF_SB_HI + bByte + ko + 16 * ROWB);
            LDSM4(bl[0], bl[1], bl[2], bl[3], st + OFF_SB_LO + bByte + ko);
            LDSM4(bl[4], bl[5], bl[6], bl[7], st + OFF_SB_LO + bByte + ko + 16 * ROWB);
            #pragma unroll
            for (int t = 0; t < 4; ++t)
                LDSM4(af[4*t], af[4*t+1], af[4*t+2], af[4*t+3],
                      st + OFF_SA_HI + aByte + ko + (uint32_t)t * 16 * ROWB);

            #pragma unroll
            for (int t = 0; t < 4; ++t)
                #pragma unroll
                for (int u = 0; u < 4; ++u) {
                    const int p = u >> 1, q = u & 1;
                    MMA(acc[t][u], &af[4*t], bh[4*p + q], bh[4*p + q + 2]);
                }
            #pragma unroll
            for (int t = 0; t < 4; ++t)
                #pragma unroll
                for (int u = 0; u < 4; ++u) {
                    const int p = u >> 1, q = u & 1;
                    MMA(acc[t][u], &af[4*t], bl[4*p + q], bl[4*p + q + 2]);
                }
            #pragma unroll
            for (int t = 0; t < 4; ++t)
                LDSM4(af[4*t], af[4*t+1], af[4*t+2], af[4*t+3],
                      st + OFF_SA_LO + aByte + ko + (uint32_t)t * 16 * ROWB);
            #pragma unroll
            for (int t = 0; t < 4; ++t)
                #pragma unroll
                for (int u = 0; u < 4; ++u) {
                    const int p = u >> 1, q = u & 1;
                    MMA(acc[t][u], &af[4*t], bh[4*p + q], bh[4*p + q + 2]);
                }
        }
    }

    // ---------------- epilogue ----------------------------------------------
    const int l4  = lane >> 2;
    const int lc2 = (lane & 3) * 2;
    #pragma unroll
    for (int u = 0; u < 4; ++u) {
        const int col = bcol + wn * 32 + u * 8 + lc2;
        float b0 = 0.0f, b1 = 0.0f;
        if (BIAS) {
            b0 = __ldg(bias + col);
            b1 = __ldg(bias + col + 1);
        }
        #pragma unroll
        for (int t = 0; t < 4; ++t)
            #pragma unroll
            for (int h = 0; h < 2; ++h) {
                const int row = brow + wm * 64 + t * 16 + h * 8 + l4;
                if (BOUND && (row >= M || col >= N)) continue;
                float v0 = acc[t][u][2*h + 0];
                float v1 = acc[t][u][2*h + 1];
                if (BIAS) { v0 += b0; v1 += b1; }
                if (RELU) { v0 = fmaxf(v0, 0.0f); v1 = fmaxf(v1, 0.0f); }
                const size_t o = (size_t)row * ldc + col;
                if (STF32) {
                    float2 f2; f2.x = v0; f2.y = v1;
                    *(float2*)(C + o) = f2;
                }
                if (HILO) {
                    __nv_bfloat162 hh = __floats2bfloat162_rn(v0, v1);
                    *(__nv_bfloat162*)(Chi + o) = hh;
                    __nv_bfloat162 ll = __floats2bfloat162_rn(
                        v0 - __bfloat162float(hh.x), v1 - __bfloat162float(hh.y));
                    *(__nv_bfloat162*)(Clo + o) = ll;
                }
            }
    }
}

// ---------------------------------------------------------------------------
// kernel_launch
// ---------------------------------------------------------------------------
extern "C" void kernel_launch(void* const* d_in, const int* in_sizes, int n_in,
                              void* d_out, int out_size)
{
    const float* x  = (const float*)d_in[0];   // [4096, 2048]
    const float* V1 = (const float*)d_in[1];   // [5794, 2897]
    const float* V2 = (const float*)d_in[2];   // [5794, 2897]
    float* out = (float*)d_out;                // [4096, 2048]

    bf16 *v1h, *v1l, *v2h, *v2l, *vh, *vl, *xh, *xl, *hh, *hl;
    float* gb;
    cudaGetSymbolAddress((void**)&v1h, g_V1hi);
    cudaGetSymbolAddress((void**)&v1l, g_V1lo);
    cudaGetSymbolAddress((void**)&v2h, g_V2hi);
    cudaGetSymbolAddress((void**)&v2l, g_V2lo);
    cudaGetSymbolAddress((void**)&vh,  g_Vhi);
    cudaGetSymbolAddress((void**)&vl,  g_Vlo);
    cudaGetSymbolAddress((void**)&xh,  g_xhi);
    cudaGetSymbolAddress((void**)&xl,  g_xlo);
    cudaGetSymbolAddress((void**)&hh,  g_hhi);
    cudaGetSymbolAddress((void**)&hl,  g_hlo);
    cudaGetSymbolAddress((void**)&gb,  g_bias);

    cudaFuncSetAttribute(gemm_mma<false, false, false, true,  true>,
                         cudaFuncAttributeMaxDynamicSharedMemorySize, SMEM_TOTAL);
    cudaFuncSetAttribute(gemm_mma<true,  true,  false, true,  false>,
                         cudaFuncAttributeMaxDynamicSharedMemorySize, SMEM_TOTAL);
    cudaFuncSetAttribute(gemm_mma<true,  false, true,  false, false>,
                         cudaFuncAttributeMaxDynamicSharedMemorySize, SMEM_TOTAL);

    // 1. split inputs into hi/lo bf16 planes; biases via fp32 dot products
    {
        int total = SZN_PAD * SZK_PAD;
        split_pad<<<(total + 255) / 256, 256>>>(V1, v1h, v1l, SZN, SZM, SZN_PAD, SZK_PAD);
        split_pad<<<(total + 255) / 256, 256>>>(V2, v2h, v2l, SZN, SZM, SZN_PAD, SZK_PAD);
        int totx = BATCH * D_IN;
        split_pad<<<(totx + 255) / 256, 256>>>(x, xh, xl, BATCH, D_IN, BATCH, D_IN);
        bias_kernel<<<(D_FF + D_OUT) / 8, 256>>>(V1, V2, gb);
    }

    // 2. V = V1 @ V2^T : hi/lo planes (bounded stores, ldc=5794)
    gemm_mma<false, false, false, true, true>
        <<<dim3(SZN_PAD / 128, SZN_PAD / 128), 256, SMEM_TOTAL>>>(
        v1h, v1l, v2h, v2l, nullptr,
        nullptr, vh, vl,
        SZN, SZN, SZK_PAD, SZK_PAD, SZK_PAD, SZN);

    // 3. h = relu(x @ W1^T + b1) : hi/lo planes
    gemm_mma<true, true, false, true, false>
        <<<dim3(D_FF / 128, BATCH / 128), 256, SMEM_TOTAL>>>(
        xh, xl, vh /*W1hi*/, vl /*W1lo*/, gb,
        nullptr, hh, hl,
        BATCH, D_FF, D_IN, D_IN, D_IN, D_FF);

    // 4. out = h @ W2^T + b2 : fp32
    gemm_mma<true, false, true, false, false>
        <<<dim3(D_OUT / 128, BATCH / 128), 256, SMEM_TOTAL>>>(
        hh, hl, vh + OFF_W2, vl + OFF_W2, gb + D_FF,
        out, nullptr, nullptr,
        BATCH, D_OUT, D_FF, D_FF, D_FF, D_OUT);
}

// round 5
// speedup vs baseline: 1.2504x; 1.2504x over previous
#include <cuda_runtime.h>
#include <cuda_bf16.h>
#include <cstdint>

// ---------------------------------------------------------------------------
// FeatherNet via mma.sync bf16 HMMA. Split-bf16 3-pass (hi*hi + hi*lo + lo*hi)
// fp32 accumulate. Round-3 pipeline (4-stage, K16, wait_group 2) + round-4
// structural wins (fp32 bias kernel, no fp32 V plane, light GEMM1 epilogue).
// ---------------------------------------------------------------------------

using bf16 = __nv_bfloat16;

#define D_IN   2048
#define D_FF   8192
#define D_OUT  2048
#define BATCH  4096
#define SZN    5794
#define SZM    2897
#define SZN_PAD 5888            // 46*128
#define SZK_PAD 2944            // 184*16

#define OFF_B1 (D_FF * D_IN)                // 16777216
#define OFF_W2 (OFF_B1 + D_FF)              // 16785408
#define OFF_B2 (OFF_W2 + D_OUT * D_FF)      // 33562624

// ---------------- device scratch -------------------------------------------
__device__ bf16  g_V1hi[(size_t)SZN_PAD * SZK_PAD];
__device__ bf16  g_V1lo[(size_t)SZN_PAD * SZK_PAD];
__device__ bf16  g_V2hi[(size_t)SZN_PAD * SZK_PAD];
__device__ bf16  g_V2lo[(size_t)SZN_PAD * SZK_PAD];
__device__ bf16  g_Vhi[(size_t)SZN * SZN];
__device__ bf16  g_Vlo[(size_t)SZN * SZN];
__device__ bf16  g_xhi[(size_t)BATCH * D_IN];
__device__ bf16  g_xlo[(size_t)BATCH * D_IN];
__device__ bf16  g_hhi[(size_t)BATCH * D_FF];
__device__ bf16  g_hlo[(size_t)BATCH * D_FF];
__device__ float g_bias[D_FF + D_OUT];      // [b1 | b2]

// ---------------- PTX helpers ----------------------------------------------
__device__ __forceinline__ uint32_t smem_u32(const void* p) {
    uint32_t a;
    asm("{ .reg .u64 t; cvta.to.shared.u64 t, %1; cvt.u32.u64 %0, t; }"
        : "=r"(a) : "l"(p));
    return a;
}

#define CP16(sm, gp) \
    asm volatile("cp.async.cg.shared.global [%0], [%1], 16;" :: "r"(sm), "l"(gp))
#define CPCOMMIT() asm volatile("cp.async.commit_group;" ::: "memory")
#define CPWAIT2()  asm volatile("cp.async.wait_group 2;" ::: "memory")

#define LDSM4(r0, r1, r2, r3, addr) \
    asm volatile("ldmatrix.sync.aligned.m8n8.x4.shared.b16 {%0,%1,%2,%3}, [%4];" \
                 : "=r"(r0), "=r"(r1), "=r"(r2), "=r"(r3) : "r"(addr))

#define MMA(d, a, b0r, b1r) \
    asm volatile("mma.sync.aligned.m16n8k16.row.col.f32.bf16.bf16.f32 " \
                 "{%0,%1,%2,%3}, {%4,%5,%6,%7}, {%8,%9}, {%0,%1,%2,%3};" \
                 : "+f"((d)[0]), "+f"((d)[1]), "+f"((d)[2]), "+f"((d)[3]) \
                 : "r"((a)[0]), "r"((a)[1]), "r"((a)[2]), "r"((a)[3]), \
                   "r"(b0r), "r"(b1r))

// ---------------- tiling (round-3 proven) -----------------------------------
#define ROWB      48
#define PLANE     (128 * ROWB)          // 6144 B
#define OFF_SA_HI 0
#define OFF_SA_LO PLANE
#define OFF_SB_HI (2 * PLANE)
#define OFF_SB_LO (3 * PLANE)
#define STAGE     (4 * PLANE)           // 24576 B
#define NSTAGE    4
#define SMEM_TOTAL (NSTAGE * STAGE)     // 98304 B

// ---------------------------------------------------------------------------
__global__ void split_pad(const float* __restrict__ src,
                          bf16* __restrict__ hi, bf16* __restrict__ lo,
                          int rows, int cols, int prows, int pcols)
{
    int idx = blockIdx.x * blockDim.x + threadIdx.x;
    int total = prows * pcols;
    if (idx >= total) return;
    int r = idx / pcols;
    int c = idx - r * pcols;
    float v = (r < rows && c < cols) ? src[(size_t)r * cols + c] : 0.0f;
    bf16 h = __float2bfloat16(v);
    hi[idx] = h;
    lo[idx] = __float2bfloat16(v - __bfloat162float(h));
}

// ---------------------------------------------------------------------------
// bias: out[j] = dot(V1[r,:], V2[c,:]) fp32, warp per output.
// ---------------------------------------------------------------------------
__global__ void bias_kernel(const float* __restrict__ V1, const float* __restrict__ V2,
                            float* __restrict__ biases)
{
    int w = (blockIdx.x * blockDim.x + threadIdx.x) >> 5;
    int lane = threadIdx.x & 31;
    if (w >= D_FF + D_OUT) return;
    size_t flat = (w < D_FF) ? ((size_t)OFF_B1 + w) : ((size_t)OFF_B2 + (w - D_FF));
    int r = (int)(flat / SZN);
    int c = (int)(flat - (size_t)r * SZN);
    const float* a = V1 + (size_t)r * SZM;
    const float* b = V2 + (size_t)c * SZM;
    float s = 0.0f;
    for (int k = lane; k < SZM; k += 32)
        s = fmaf(__ldg(a + k), __ldg(b + k), s);
    #pragma unroll
    for (int o = 16; o > 0; o >>= 1)
        s += __shfl_xor_sync(0xFFFFFFFFu, s, o);
    if (lane == 0) biases[w] = s;
}

// ---------------------------------------------------------------------------
// split-bf16 HMMA GEMM: C[M,N] = A @ B^T (+bias) (relu)
// ---------------------------------------------------------------------------
template<bool BIAS, bool RELU, bool STF32, bool HILO, bool BOUND>
__global__ __launch_bounds__(256, 1)
void gemm_mma(const bf16* __restrict__ Ahi, const bf16* __restrict__ Alo,
              const bf16* __restrict__ Bhi, const bf16* __restrict__ Blo,
              const float* __restrict__ bias,
              float* __restrict__ C, bf16* __restrict__ Chi, bf16* __restrict__ Clo,
              int M, int N, int K, int lda, int ldb, int ldc)
{
    extern __shared__ char smem[];
    const uint32_t sb = smem_u32(smem);
    const int tid  = threadIdx.x;
    const int lane = tid & 31, wid = tid >> 5;
    const int wm = wid >> 2;        // 0..1 : 64 rows
    const int wn = wid & 3;         // 0..3 : 32 cols
    const int brow = blockIdx.y * 128;
    const int bcol = blockIdx.x * 128;

    // cp.async geometry: thread -> (row, 16B chunk)
    const int lrow = tid >> 1, lch = tid & 1;
    const bf16* gAh = Ahi + (size_t)(brow + lrow) * lda + lch * 8;
    const bf16* gAl = Alo + (size_t)(brow + lrow) * lda + lch * 8;
    const bf16* gBh = Bhi + (size_t)(bcol + lrow) * ldb + lch * 8;
    const bf16* gBl = Blo + (size_t)(bcol + lrow) * ldb + lch * 8;
    const uint32_t stByte = (uint32_t)(lrow * ROWB + lch * 16);

    const uint32_t aByte = (uint32_t)((wm * 64 + (lane & 15)) * ROWB + (lane >> 4) * 16);
    const uint32_t bByte = (uint32_t)((wn * 32 + (lane & 15)) * ROWB + (lane >> 4) * 16);

    float acc[4][4][4];
    #pragma unroll
    for (int t = 0; t < 4; ++t)
        #pragma unroll
        for (int u = 0; u < 4; ++u)
            #pragma unroll
            for (int e = 0; e < 4; ++e) acc[t][u][e] = 0.0f;

    const int nk = K >> 4;

    auto issue = [&](int kb) {
        const uint32_t st = sb + (uint32_t)(kb & (NSTAGE - 1)) * STAGE + stByte;
        const size_t go = (size_t)kb * 16;
        CP16(st + OFF_SA_HI, gAh + go);
        CP16(st + OFF_SA_LO, gAl + go);
        CP16(st + OFF_SB_HI, gBh + go);
        CP16(st + OFF_SB_LO, gBl + go);
        CPCOMMIT();
    };

    issue(0); issue(1); issue(2);

    #pragma unroll 1
    for (int i = 0; i < nk; ++i) {
        CPWAIT2();
        __syncthreads();
        const uint32_t st = sb + (uint32_t)(i & (NSTAGE - 1)) * STAGE;

        uint32_t bh[8], bl[8], af[16];
        LDSM4(bh[0], bh[1], bh[2], bh[3], st + OFF_SB_HI + bByte);
        LDSM4(bh[4], bh[5], bh[6], bh[7], st + OFF_SB_HI + bByte + 16 * ROWB);
        LDSM4(bl[0], bl[1], bl[2], bl[3], st + OFF_SB_LO + bByte);
        LDSM4(bl[4], bl[5], bl[6], bl[7], st + OFF_SB_LO + bByte + 16 * ROWB);
        #pragma unroll
        for (int t = 0; t < 4; ++t)
            LDSM4(af[4*t], af[4*t+1], af[4*t+2], af[4*t+3],
                  st + OFF_SA_HI + aByte + (uint32_t)t * 16 * ROWB);

        // pass 1: Ahi * Bhi
        #pragma unroll
        for (int t = 0; t < 4; ++t)
            #pragma unroll
            for (int u = 0; u < 4; ++u) {
                const int p = u >> 1, q = u & 1;
                MMA(acc[t][u], &af[4*t], bh[4*p + q], bh[4*p + q + 2]);
            }
        // pass 2: Ahi * Blo
        #pragma unroll
        for (int t = 0; t < 4; ++t)
            #pragma unroll
            for (int u = 0; u < 4; ++u) {
                const int p = u >> 1, q = u & 1;
                MMA(acc[t][u], &af[4*t], bl[4*p + q], bl[4*p + q + 2]);
            }
        // pass 3: Alo * Bhi (reuse af registers)
        #pragma unroll
        for (int t = 0; t < 4; ++t)
            LDSM4(af[4*t], af[4*t+1], af[4*t+2], af[4*t+3],
                  st + OFF_SA_LO + aByte + (uint32_t)t * 16 * ROWB);
        #pragma unroll
        for (int t = 0; t < 4; ++t)
            #pragma unroll
            for (int u = 0; u < 4; ++u) {
                const int p = u >> 1, q = u & 1;
                MMA(acc[t][u], &af[4*t], bh[4*p + q], bh[4*p + q + 2]);
            }

        if (i + 3 < nk) issue(i + 3);
    }

    // ---------------- epilogue (registers -> global, direct) ----------------
    const int l4  = lane >> 2;
    const int lc2 = (lane & 3) * 2;
    #pragma unroll
    for (int u = 0; u < 4; ++u) {
        const int col = bcol + wn * 32 + u * 8 + lc2;
        float b0 = 0.0f, b1 = 0.0f;
        if (BIAS) {
            b0 = __ldg(bias + col);
            b1 = __ldg(bias + col + 1);
        }
        #pragma unroll
        for (int t = 0; t < 4; ++t)
            #pragma unroll
            for (int h = 0; h < 2; ++h) {
                const int row = brow + wm * 64 + t * 16 + h * 8 + l4;
                // N even & col even -> pair [col, col+1] fully inside when col < N
                if (BOUND && (row >= M || col >= N)) continue;
                float v0 = acc[t][u][2*h + 0];
                float v1 = acc[t][u][2*h + 1];
                if (BIAS) { v0 += b0; v1 += b1; }
                if (RELU) { v0 = fmaxf(v0, 0.0f); v1 = fmaxf(v1, 0.0f); }
                const size_t o = (size_t)row * ldc + col;
                if (STF32) {
                    float2 f2; f2.x = v0; f2.y = v1;
                    *(float2*)(C + o) = f2;
                }
                if (HILO) {
                    __nv_bfloat162 hh = __floats2bfloat162_rn(v0, v1);
                    *(__nv_bfloat162*)(Chi + o) = hh;
                    __nv_bfloat162 ll = __floats2bfloat162_rn(
                        v0 - __bfloat162float(hh.x), v1 - __bfloat162float(hh.y));
                    *(__nv_bfloat162*)(Clo + o) = ll;
                }
            }
    }
}

// ---------------------------------------------------------------------------
// kernel_launch
// ---------------------------------------------------------------------------
extern "C" void kernel_launch(void* const* d_in, const int* in_sizes, int n_in,
                              void* d_out, int out_size)
{
    const float* x  = (const float*)d_in[0];   // [4096, 2048]
    const float* V1 = (const float*)d_in[1];   // [5794, 2897]
    const float* V2 = (const float*)d_in[2];   // [5794, 2897]
    float* out = (float*)d_out;                // [4096, 2048]

    bf16 *v1h, *v1l, *v2h, *v2l, *vh, *vl, *xh, *xl, *hh, *hl;
    float* gb;
    cudaGetSymbolAddress((void**)&v1h, g_V1hi);
    cudaGetSymbolAddress((void**)&v1l, g_V1lo);
    cudaGetSymbolAddress((void**)&v2h, g_V2hi);
    cudaGetSymbolAddress((void**)&v2l, g_V2lo);
    cudaGetSymbolAddress((void**)&vh,  g_Vhi);
    cudaGetSymbolAddress((void**)&vl,  g_Vlo);
    cudaGetSymbolAddress((void**)&xh,  g_xhi);
    cudaGetSymbolAddress((void**)&xl,  g_xlo);
    cudaGetSymbolAddress((void**)&hh,  g_hhi);
    cudaGetSymbolAddress((void**)&hl,  g_hlo);
    cudaGetSymbolAddress((void**)&gb,  g_bias);

    cudaFuncSetAttribute(gemm_mma<false, false, false, true,  true>,
                         cudaFuncAttributeMaxDynamicSharedMemorySize, SMEM_TOTAL);
    cudaFuncSetAttribute(gemm_mma<true,  true,  false, true,  false>,
                         cudaFuncAttributeMaxDynamicSharedMemorySize, SMEM_TOTAL);
    cudaFuncSetAttribute(gemm_mma<true,  false, true,  false, false>,
                         cudaFuncAttributeMaxDynamicSharedMemorySize, SMEM_TOTAL);

    // 1. split inputs into hi/lo planes; biases via fp32 dot products
    {
        int total = SZN_PAD * SZK_PAD;
        split_pad<<<(total + 255) / 256, 256>>>(V1, v1h, v1l, SZN, SZM, SZN_PAD, SZK_PAD);
        split_pad<<<(total + 255) / 256, 256>>>(V2, v2h, v2l, SZN, SZM, SZN_PAD, SZK_PAD);
        int totx = BATCH * D_IN;
        split_pad<<<(totx + 255) / 256, 256>>>(x, xh, xl, BATCH, D_IN, BATCH, D_IN);
        bias_kernel<<<(D_FF + D_OUT) / 8, 256>>>(V1, V2, gb);
    }

    // 2. V = V1 @ V2^T : hi/lo planes (bounded bf162 stores, ldc=5794 even)
    gemm_mma<false, false, false, true, true>
        <<<dim3(SZN_PAD / 128, SZN_PAD / 128), 256, SMEM_TOTAL>>>(
        v1h, v1l, v2h, v2l, nullptr,
        nullptr, vh, vl,
        SZN, SZN, SZK_PAD, SZK_PAD, SZK_PAD, SZN);

    // 3. h = relu(x @ W1^T + b1) : hi/lo planes
    gemm_mma<true, true, false, true, false>
        <<<dim3(D_FF / 128, BATCH / 128), 256, SMEM_TOTAL>>>(
        xh, xl, vh /*W1hi*/, vl /*W1lo*/, gb,
        nullptr, hh, hl,
        BATCH, D_FF, D_IN, D_IN, D_IN, D_FF);

    // 4. out = h @ W2^T + b2 : fp32
    gemm_mma<true, false, true, false, false>
        <<<dim3(D_OUT / 128, BATCH / 128), 256, SMEM_TOTAL>>>(
        hh, hl, vh + OFF_W2, vl + OFF_W2, gb + D_FF,
        out, nullptr, nullptr,
        BATCH, D_OUT, D_FF, D_FF, D_FF, D_OUT);
}